// round 5
// baseline (speedup 1.0000x reference)
#include <cuda_runtime.h>
#include <stdint.h>

// Shapes:
//   core0: (1, 50, 8, 16)   -> A[v0][e0][r1]   (A tile per v0 = 128 floats)
//   core1: (16, 50, 4, 16)  -> B[r1][v1][e1][r2]
//   core2: (16, 80, 4, 1)   -> C[r2][v2][e2]
//   indices: 8192, vocab 200000 = (50,50,80) row-major
//   out[n][e0*16+e1*4+e2], fp32
//
// One block = 8 indices. Phases:
//   (a) each warp w reads its index, loads A(v0) tile (32 float4) -> shA
//   (b) threads<128 stage C slices for the 8 tiles -> sc[t][r2] (float4)
//   (c) 512 H rows (8 tiles x 64 rows), 2 rows/thread:
//       H4[t][r1][e1] = sum_r2 B[r1,v1_t,e1,r2] * C4[t][r2]   -> shH
//   (d) warp w: out = A [8x16] @ H_w [16x16], all operands in smem.

#define NV1 50
#define NV2 80
#define RANK 16
#define NIDX 8192

__global__ __launch_bounds__(256) void tt_fused(
    const void* __restrict__ idx_raw,
    const float* __restrict__ core0,
    const float* __restrict__ core1,
    const float* __restrict__ core2,
    float* __restrict__ out)
{
    __shared__ __align__(16) float4 shA[8 * 32];   // 8 A tiles (4 KB)
    __shared__ __align__(16) float4 sc[8][16];     // 8 C slices (2 KB)
    __shared__ __align__(16) float4 shH[8 * 64];   // 8 H tiles (8 KB)

    const int tid  = threadIdx.x;
    const int w    = tid >> 5;
    const int lane = tid & 31;
    const int g    = blockIdx.x * 8;               // base index id

    // dtype sniff: int64 vs int32 (values < 2e5 -> int64 high words all zero)
    const int* i32 = (const int*)idx_raw;
    const bool is64 = __all_sync(0xffffffffu, i32[2 * lane + 1] == 0);
    const long long* i64 = (const long long*)idx_raw;

    // ---- (a) own-warp index + A tile -> shA -------------------------------
    const int iv_w = is64 ? (int)i64[g + w] : i32[g + w];
    const int v0_w = iv_w / (NV1 * NV2);
    shA[w * 32 + lane] = __ldg((const float4*)(core0 + (size_t)v0_w * 128) + lane);

    // ---- (b) C slices -----------------------------------------------------
    if (tid < 128) {
        const int t  = tid >> 4;
        const int r2 = tid & 15;
        const int iv = is64 ? (int)i64[g + t] : i32[g + t];
        const int v2 = iv % NV2;
        sc[t][r2] = __ldg((const float4*)(core2 + ((size_t)r2 * NV2 + v2) * 4));
    }
    __syncthreads();

    // ---- (c) H rows: 2 per thread ----------------------------------------
#pragma unroll
    for (int s = 0; s < 2; ++s) {
        const int row = tid + 256 * s;             // 0..511
        const int t   = row >> 6;
        const int j   = row & 63;
        const int r1  = j >> 2;
        const int e1  = j & 3;

        const int iv  = is64 ? (int)i64[g + t] : i32[g + t];
        const int rem = iv - (iv / (NV1 * NV2)) * (NV1 * NV2);
        const int v1  = rem / NV2;

        const float4* B4 = (const float4*)(core1 + (((size_t)r1 * NV1 + v1) * 4 + e1) * RANK);
        const float4 b0 = __ldg(&B4[0]);
        const float4 b1 = __ldg(&B4[1]);
        const float4 b2 = __ldg(&B4[2]);
        const float4 b3 = __ldg(&B4[3]);
        const float bb[RANK] = { b0.x, b0.y, b0.z, b0.w,  b1.x, b1.y, b1.z, b1.w,
                                 b2.x, b2.y, b2.z, b2.w,  b3.x, b3.y, b3.z, b3.w };

        float4 acc = make_float4(0.f, 0.f, 0.f, 0.f);
#pragma unroll
        for (int r2 = 0; r2 < RANK; ++r2) {
            const float4 c4 = sc[t][r2];           // warp-uniform broadcast LDS
            acc.x = fmaf(bb[r2], c4.x, acc.x);
            acc.y = fmaf(bb[r2], c4.y, acc.y);
            acc.z = fmaf(bb[r2], c4.z, acc.z);
            acc.w = fmaf(bb[r2], c4.w, acc.w);
        }
        shH[row] = acc;                            // conflict-free STS.128
    }
    __syncthreads();

    // ---- (d) gather: warp w computes out row for index g+w ---------------
    const int e0 = lane >> 2;
    const int q  = lane & 3;

    float a[RANK];
#pragma unroll
    for (int k = 0; k < 4; ++k) {
        const float4 t4 = shA[w * 32 + e0 * 4 + k];
        a[4 * k + 0] = t4.x; a[4 * k + 1] = t4.y; a[4 * k + 2] = t4.z; a[4 * k + 3] = t4.w;
    }

    float4 acc = make_float4(0.f, 0.f, 0.f, 0.f);
#pragma unroll
    for (int r1 = 0; r1 < RANK; ++r1) {
        const float4 h = shH[w * 64 + r1 * 4 + q];
        acc.x = fmaf(a[r1], h.x, acc.x);
        acc.y = fmaf(a[r1], h.y, acc.y);
        acc.z = fmaf(a[r1], h.z, acc.z);
        acc.w = fmaf(a[r1], h.w, acc.w);
    }

    ((float4*)(out + (size_t)(g + w) * 128))[lane] = acc;
}

// Inputs (metadata order): indices, core0, core1, core2
extern "C" void kernel_launch(void* const* d_in, const int* in_sizes, int n_in,
                              void* d_out, int out_size)
{
    const void*  indices = d_in[0];
    const float* core0   = (const float*)d_in[1];
    const float* core1   = (const float*)d_in[2];
    const float* core2   = (const float*)d_in[3];
    float* out = (float*)d_out;

    tt_fused<<<NIDX / 8, 256>>>(indices, core0, core1, core2, out);
}

// round 6
// speedup vs baseline: 1.1387x; 1.1387x over previous
#include <cuda_runtime.h>
#include <stdint.h>

// Shapes:
//   core0: (1, 50, 8, 16)   -> A[v0][e0][r1]   (A tile per v0 = 128 floats)
//   core1: (16, 50, 4, 16)  -> B[r1][v1][e1][r2]
//   core2: (16, 80, 4, 1)   -> C[r2][v2][e2]
//   indices: 8192, vocab 200000 = (50,50,80) row-major
//   out: (8192, 128) fp32, embed index = e0*16 + e1*4 + e2

#define NV1 50
#define NV2 80
#define RANK 16
#define NIDX 8192

// H[(v1*80+v2)][r1][e1*4+e2]: 4000 * 256 floats = 4 MB (L2-resident)
__device__ float g_H[NV1 * NV2 * RANK * 16];

// ---------------------------------------------------------------------------
// Kernel 1: warp per (v1,v2) pair.
//   H[r1][e1*4+e2] = sum_r2 B[r1,v1,e1,r2] * C[r2,v2,e2]
// launch_bounds(256,4) -> 64-reg budget so both B-row load batches pipeline.
// ---------------------------------------------------------------------------
__global__ __launch_bounds__(256, 4) void tt_build_H(
    const float* __restrict__ core1,   // (16,50,4,16)
    const float* __restrict__ core2)   // (16,80,4,1)
{
    __shared__ __align__(16) float sc[8][64];   // per-warp C slice [r2*4+e2]

    const int w    = threadIdx.x >> 5;
    const int lane = threadIdx.x & 31;
    const int pair = blockIdx.x * 8 + w;        // 0..3999, grid exact
    const int v1   = pair / NV2;
    const int v2   = pair - v1 * NV2;

    if (lane < RANK) {
        const float4 c = __ldg((const float4*)(core2 + ((size_t)lane * NV2 + v2) * 4));
        *(float4*)&sc[w][lane * 4] = c;
    }
    __syncwarp();

    float* hout = g_H + (size_t)pair * (RANK * 16);

#pragma unroll
    for (int pass = 0; pass < 2; ++pass) {
        const int j  = lane + 32 * pass;        // H row id 0..63 (float4 units)
        const int r1 = j >> 2;
        const int e1 = j & 3;

        const float4* B4 = (const float4*)(core1 + (((size_t)r1 * NV1 + v1) * 4 + e1) * RANK);
        const float4 b0 = __ldg(&B4[0]);
        const float4 b1 = __ldg(&B4[1]);
        const float4 b2 = __ldg(&B4[2]);
        const float4 b3 = __ldg(&B4[3]);
        const float bb[RANK] = { b0.x, b0.y, b0.z, b0.w,  b1.x, b1.y, b1.z, b1.w,
                                 b2.x, b2.y, b2.z, b2.w,  b3.x, b3.y, b3.z, b3.w };

        float4 acc = make_float4(0.f, 0.f, 0.f, 0.f);
#pragma unroll
        for (int r2 = 0; r2 < RANK; ++r2) {
            const float4 c4 = *(const float4*)&sc[w][r2 * 4];
            acc.x = fmaf(bb[r2], c4.x, acc.x);
            acc.y = fmaf(bb[r2], c4.y, acc.y);
            acc.z = fmaf(bb[r2], c4.z, acc.z);
            acc.w = fmaf(bb[r2], c4.w, acc.w);
        }
        ((float4*)hout)[j] = acc;               // coalesced STG.128
    }
}

// ---------------------------------------------------------------------------
// Kernel 2: warp per index, cooperative tile staging.
//   3 dedup'd coalesced LDG.128/lane stage A (32 f4) + H (64 f4) into smem,
//   then compute from broadcast, conflict-free LDS.128.
//   Lane l: e0=l>>2, q=l&3 owns out[l*4 .. l*4+3].
// launch_bounds(256,4) -> 64-reg budget: LDS batch fully pipelined ahead of FMAs.
// ---------------------------------------------------------------------------
__global__ __launch_bounds__(256, 4) void tt_gather(
    const void* __restrict__ idx_raw,
    const float* __restrict__ core0,   // (1,50,8,16)
    float* __restrict__ out)           // (8192,128)
{
    // Per-warp: [0..31] = A tile, [32..95] = H tile (float4 units)
    __shared__ __align__(16) float4 sh[8][96];

    const int w    = threadIdx.x >> 5;
    const int lane = threadIdx.x & 31;
    const int warp = blockIdx.x * 8 + w;

    // dtype sniff: int64 vs int32 (all values < 2e5 -> high words all zero)
    const int* i32 = (const int*)idx_raw;
    const int hw = i32[2 * lane + 1];
    const bool is64 = __all_sync(0xffffffffu, hw == 0);

    int iv;
    if (is64) iv = (int)((const long long*)idx_raw)[warp];
    else      iv = i32[warp];

    const int v0  = iv / (NV1 * NV2);
    const int rem = iv - v0 * (NV1 * NV2);
    const int v1  = rem / NV2;
    const int v2  = rem - v1 * NV2;

    // 3 independent, dedup'd, coalesced tile loads.
    const float4* At = (const float4*)(core0 + (size_t)v0 * 128);              // 32 f4
    const float4* Ht = (const float4*)(g_H + ((size_t)(v1 * NV2 + v2)) * 256); // 64 f4
    const float4 av = __ldg(&At[lane]);
    const float4 h0 = __ldg(&Ht[lane]);
    const float4 h1 = __ldg(&Ht[lane + 32]);
    sh[w][lane]      = av;
    sh[w][32 + lane] = h0;
    sh[w][64 + lane] = h1;
    __syncwarp();

    const int e0 = lane >> 2;
    const int q  = lane & 3;

    // A row e0: 4 LDS.128, 4-lane broadcast each (conflict-free).
    float a[RANK];
#pragma unroll
    for (int k = 0; k < 4; ++k) {
        const float4 t = sh[w][e0 * 4 + k];
        a[4 * k + 0] = t.x; a[4 * k + 1] = t.y; a[4 * k + 2] = t.z; a[4 * k + 3] = t.w;
    }

    // H column quarter q: 16 LDS.128, 8-lane broadcast each (conflict-free).
    float4 hreg[RANK];
#pragma unroll
    for (int r1 = 0; r1 < RANK; ++r1) hreg[r1] = sh[w][32 + r1 * 4 + q];

    float4 acc = make_float4(0.f, 0.f, 0.f, 0.f);
#pragma unroll
    for (int r1 = 0; r1 < RANK; ++r1) {
        acc.x = fmaf(a[r1], hreg[r1].x, acc.x);
        acc.y = fmaf(a[r1], hreg[r1].y, acc.y);
        acc.z = fmaf(a[r1], hreg[r1].z, acc.z);
        acc.w = fmaf(a[r1], hreg[r1].w, acc.w);
    }

    ((float4*)(out + (size_t)warp * 128))[lane] = acc;
}

// Inputs (metadata order): indices, core0, core1, core2
extern "C" void kernel_launch(void* const* d_in, const int* in_sizes, int n_in,
                              void* d_out, int out_size)
{
    const void*  indices = d_in[0];
    const float* core0   = (const float*)d_in[1];
    const float* core1   = (const float*)d_in[2];
    const float* core2   = (const float*)d_in[3];
    float* out = (float*)d_out;

    tt_build_H<<<(NV1 * NV2) / 8, 256>>>(core1, core2);
    tt_gather<<<(NIDX * 32) / 256, 256>>>(indices, core0, out);
}

// round 7
// speedup vs baseline: 1.3187x; 1.1580x over previous
#include <cuda_runtime.h>
#include <stdint.h>

// Shapes:
//   core0: (1, 50, 8, 16)   -> A[v0][e0][r1]   (A tile per v0 = 128 floats)
//   core1: (16, 50, 4, 16)  -> B[r1][v1][e1][r2] (per-v1 slice = 16 chunks of 64 floats)
//   core2: (16, 80, 4, 1)   -> C[r2][v2][e2]
//   indices: 8192, vocab 200000 = (50,50,80) row-major
//   out: (8192, 128) fp32, embed index = e0*16 + e1*4 + e2

#define NV1 50
#define NV2 80
#define RANK 16
#define NIDX 8192

// H[(v1*80+v2)][r1][e1*4+e2]: 4000 * 256 floats = 4 MB (L2-resident)
__device__ float g_H[NV1 * NV2 * RANK * 16];

// ---------------------------------------------------------------------------
// Kernel 1: block = 8 pairs (all share v1 since 80 % 8 == 0).
//   Stage B[:,v1] (16 x 64 floats) in smem once, coalesced; each warp then
//   computes its (v1,v2) tile: H[r1][e1*4+e2] = sum_r2 B[r1,v1,e1,r2]*C[r2,v2,e2]
// ---------------------------------------------------------------------------
__global__ __launch_bounds__(256) void tt_build_H(
    const float* __restrict__ core1,   // (16,50,4,16)
    const float* __restrict__ core2)   // (16,80,4,1)
{
    // B slice padded: 16 chunks of 64 floats, stride 68 (pad kills 8-way conflicts)
    __shared__ __align__(16) float sB[16 * 68];
    __shared__ __align__(16) float4 sc[8][16];   // per-warp C slice [r2]

    const int tid  = threadIdx.x;
    const int w    = tid >> 5;
    const int lane = tid & 31;
    const int pair0 = blockIdx.x * 8;            // 8 consecutive pairs, same v1
    const int v1    = pair0 / NV2;
    const int v2    = (pair0 - v1 * NV2) + w;    // this warp's v2

    // Stage B: thread (r1 = tid>>4, c4 = tid&15) loads float4 c4 of chunk r1.
    {
        const int r1 = tid >> 4;
        const int c4 = tid & 15;
        const float4 b = __ldg((const float4*)(core1 + ((size_t)r1 * NV1 + v1) * 64) + c4);
        *(float4*)&sB[r1 * 68 + c4 * 4] = b;
    }
    // Stage C slice for this warp's v2.
    if (lane < RANK)
        sc[w][lane] = __ldg((const float4*)(core2 + ((size_t)lane * NV2 + v2) * 4));
    __syncthreads();

    float* hout = g_H + (size_t)(v1 * NV2 + v2) * (RANK * 16);

#pragma unroll
    for (int pass = 0; pass < 2; ++pass) {
        const int j  = lane + 32 * pass;         // H row id 0..63 (float4 units)
        const int r1 = j >> 2;
        const int e1 = j & 3;

        // This row's 16 B values: contiguous floats in the padded chunk.
        const float* bp = &sB[r1 * 68 + e1 * 16];
        const float4 b0 = *(const float4*)(bp + 0);
        const float4 b1 = *(const float4*)(bp + 4);
        const float4 b2 = *(const float4*)(bp + 8);
        const float4 b3 = *(const float4*)(bp + 12);
        const float bb[RANK] = { b0.x, b0.y, b0.z, b0.w,  b1.x, b1.y, b1.z, b1.w,
                                 b2.x, b2.y, b2.z, b2.w,  b3.x, b3.y, b3.z, b3.w };

        float4 acc = make_float4(0.f, 0.f, 0.f, 0.f);
#pragma unroll
        for (int r2 = 0; r2 < RANK; ++r2) {
            const float4 c4 = sc[w][r2];         // broadcast LDS.128
            acc.x = fmaf(bb[r2], c4.x, acc.x);
            acc.y = fmaf(bb[r2], c4.y, acc.y);
            acc.z = fmaf(bb[r2], c4.z, acc.z);
            acc.w = fmaf(bb[r2], c4.w, acc.w);
        }
        ((float4*)hout)[j] = acc;                // coalesced STG.128
    }
}

// ---------------------------------------------------------------------------
// Kernel 2: warp handles TWO indices -> 6 independent coalesced LDG.128/lane
// staged to smem, then both 8x16 @ 16x16 products from broadcast LDS.
//   Lane l: e0=l>>2, q=l&3 owns out[l*4 .. l*4+3] of each row.
// ---------------------------------------------------------------------------
__global__ __launch_bounds__(256, 5) void tt_gather(
    const void* __restrict__ idx_raw,
    const float* __restrict__ core0,   // (1,50,8,16)
    float* __restrict__ out)           // (8192,128)
{
    // Per-warp float4 layout: [0..31]=A0 [32..95]=H0 [96..127]=A1 [128..191]=H1
    __shared__ __align__(16) float4 sh[8][192];

    const int w    = threadIdx.x >> 5;
    const int lane = threadIdx.x & 31;
    const int warp = blockIdx.x * 8 + w;
    const int i0   = warp * 2;
    const int i1   = i0 + 1;

    // dtype sniff: int64 vs int32 (all values < 2e5 -> high words all zero)
    const int* i32 = (const int*)idx_raw;
    const bool is64 = __all_sync(0xffffffffu, i32[2 * lane + 1] == 0);
    const long long* i64 = (const long long*)idx_raw;

    const int iv0 = is64 ? (int)i64[i0] : i32[i0];
    const int iv1 = is64 ? (int)i64[i1] : i32[i1];

    const int v0a  = iv0 / (NV1 * NV2);
    const int rema = iv0 - v0a * (NV1 * NV2);
    const int p0   = rema;                        // v1*80+v2 packed
    const int v0b  = iv1 / (NV1 * NV2);
    const int remb = iv1 - v0b * (NV1 * NV2);
    const int p1   = remb;

    const float4* At0 = (const float4*)(core0 + (size_t)v0a * 128);
    const float4* Ht0 = (const float4*)(g_H + (size_t)p0 * 256);
    const float4* At1 = (const float4*)(core0 + (size_t)v0b * 128);
    const float4* Ht1 = (const float4*)(g_H + (size_t)p1 * 256);

    // 6 independent, dedup'd, coalesced loads.
    const float4 a0v = __ldg(&At0[lane]);
    const float4 h00 = __ldg(&Ht0[lane]);
    const float4 h01 = __ldg(&Ht0[lane + 32]);
    const float4 a1v = __ldg(&At1[lane]);
    const float4 h10 = __ldg(&Ht1[lane]);
    const float4 h11 = __ldg(&Ht1[lane + 32]);
    sh[w][lane]       = a0v;
    sh[w][32 + lane]  = h00;
    sh[w][64 + lane]  = h01;
    sh[w][96 + lane]  = a1v;
    sh[w][128 + lane] = h10;
    sh[w][160 + lane] = h11;
    __syncwarp();

    const int e0 = lane >> 2;
    const int q  = lane & 3;

#pragma unroll
    for (int t = 0; t < 2; ++t) {
        const int abase = t ? 96 : 0;
        const int hbase = t ? 128 : 32;

        float a[RANK];
#pragma unroll
        for (int k = 0; k < 4; ++k) {
            const float4 t4 = sh[w][abase + e0 * 4 + k];
            a[4 * k + 0] = t4.x; a[4 * k + 1] = t4.y; a[4 * k + 2] = t4.z; a[4 * k + 3] = t4.w;
        }

        float4 acc = make_float4(0.f, 0.f, 0.f, 0.f);
#pragma unroll
        for (int r1 = 0; r1 < RANK; ++r1) {
            const float4 h = sh[w][hbase + r1 * 4 + q];
            acc.x = fmaf(a[r1], h.x, acc.x);
            acc.y = fmaf(a[r1], h.y, acc.y);
            acc.z = fmaf(a[r1], h.z, acc.z);
            acc.w = fmaf(a[r1], h.w, acc.w);
        }

        ((float4*)(out + (size_t)(t ? i1 : i0) * 128))[lane] = acc;
    }
}

// Inputs (metadata order): indices, core0, core1, core2
extern "C" void kernel_launch(void* const* d_in, const int* in_sizes, int n_in,
                              void* d_out, int out_size)
{
    const void*  indices = d_in[0];
    const float* core0   = (const float*)d_in[1];
    const float* core1   = (const float*)d_in[2];
    const float* core2   = (const float*)d_in[3];
    float* out = (float*)d_out;

    tt_build_H<<<(NV1 * NV2) / 8, 256>>>(core1, core2);
    tt_gather<<<NIDX / 16, 256>>>(indices, core0, out);
}